// round 5
// baseline (speedup 1.0000x reference)
#include <cuda_runtime.h>
#include <cuda_bf16.h>
#include <math.h>
#include <stdint.h>

#define D 2048
#define NA 64
#define BATCH 64
#define ROWS (BATCH * NA)        // 4096
#define LN_EPS 1e-5f
#define ID_PRESERVE 0.1f
#define SIGNAL_BOUND 1.0f
#define SINKHORN_ITERS 50

// GEMM config: CTA 128x256, BK=64 bf16 (128B rows), 4-stage cp.async, warp 64x64
#define GBM 128
#define GBN 256
#define KITERS 96                // 3 * 2048 / 64  (hh, hl, lh)
#define GSTAGES 4
#define GSTAGE_BYTES 49152       // A 16KB + B 32KB

#define SCORE_KSPLIT 4
#define SCORE_KCHUNK (D / SCORE_KSPLIT)   // 512

// ---------------- scratch (device globals; no allocation allowed) ----------
__device__ float g_normed[ROWS * D];
__device__ float g_q[ROWS * D];
__device__ float g_k[ROWS * D];
__device__ float g_v[ROWS * D];
__device__ float g_mixed[ROWS * D];
__device__ float g_spart[SCORE_KSPLIT * BATCH * NA * NA];
__device__ float g_attn[BATCH * NA * NA];
// split-bf16 operands: [hi(2048) | lo(2048)] along K per row
__device__ __nv_bfloat16 g_A2[(size_t)ROWS * 2 * D];           // [4096, 4096]
__device__ __nv_bfloat16 g_W2[3ull * D * 2 * D];               // 3 x [2048, 4096]

// ---------------- PTX helpers (sm_100 baseline only) -------------------------
__device__ __forceinline__ uint32_t smem_u32(const void* p) {
    uint32_t a;
    asm("{ .reg .u64 t; cvta.to.shared.u64 t, %1; cvt.u32.u64 %0, t; }" : "=r"(a) : "l"(p));
    return a;
}
__device__ __forceinline__ void cp16(uint32_t dst, const void* src) {
    asm volatile("cp.async.cg.shared.global [%0], [%1], 16;" :: "r"(dst), "l"(src));
}
__device__ __forceinline__ void cp_commit() { asm volatile("cp.async.commit_group;" ::: "memory"); }
template <int N>
__device__ __forceinline__ void cp_wait() { asm volatile("cp.async.wait_group %0;" :: "n"(N) : "memory"); }

#define LDSM4(r0, r1, r2, r3, addr) \
    asm volatile("ldmatrix.sync.aligned.m8n8.x4.shared.b16 {%0,%1,%2,%3}, [%4];" \
                 : "=r"(r0), "=r"(r1), "=r"(r2), "=r"(r3) : "r"(addr))

// ---------------- fp32 -> (hi, lo) bf16 split --------------------------------
__device__ __forceinline__ void split4(float4 v, uint2& hi, uint2& lo) {
    __nv_bfloat16 hx = __float2bfloat16(v.x);
    __nv_bfloat16 hy = __float2bfloat16(v.y);
    __nv_bfloat16 hz = __float2bfloat16(v.z);
    __nv_bfloat16 hw = __float2bfloat16(v.w);
    __nv_bfloat16 lx = __float2bfloat16(v.x - __bfloat162float(hx));
    __nv_bfloat16 ly = __float2bfloat16(v.y - __bfloat162float(hy));
    __nv_bfloat16 lz = __float2bfloat16(v.z - __bfloat162float(hz));
    __nv_bfloat16 lw = __float2bfloat16(v.w - __bfloat162float(hw));
    union { __nv_bfloat16 h[4]; uint2 u; } a, b;
    a.h[0] = hx; a.h[1] = hy; a.h[2] = hz; a.h[3] = hw;
    b.h[0] = lx; b.h[1] = ly; b.h[2] = lz; b.h[3] = lw;
    hi = a.u; lo = b.u;
}

// ---------------- LayerNorm + emit bf16 split --------------------------------
__global__ __launch_bounds__(256) void ln_kernel(const float* __restrict__ x,
                                                 const float* __restrict__ w,
                                                 const float* __restrict__ b) {
    __shared__ float redS[8], redQ[8];
    int row = blockIdx.x;
    int tid = threadIdx.x;
    const float4* xr = (const float4*)(x + (size_t)row * D);
    float4 v0 = xr[tid];
    float4 v1 = xr[tid + 256];
    float s  = v0.x + v0.y + v0.z + v0.w + v1.x + v1.y + v1.z + v1.w;
    float ss = v0.x*v0.x + v0.y*v0.y + v0.z*v0.z + v0.w*v0.w
             + v1.x*v1.x + v1.y*v1.y + v1.z*v1.z + v1.w*v1.w;
    #pragma unroll
    for (int o = 16; o; o >>= 1) {
        s  += __shfl_xor_sync(0xFFFFFFFFu, s, o);
        ss += __shfl_xor_sync(0xFFFFFFFFu, ss, o);
    }
    int wid = tid >> 5;
    if ((tid & 31) == 0) { redS[wid] = s; redQ[wid] = ss; }
    __syncthreads();
    float ts = 0.f, tq = 0.f;
    #pragma unroll
    for (int i = 0; i < 8; i++) { ts += redS[i]; tq += redQ[i]; }
    float mean = ts * (1.0f / D);
    float var  = tq * (1.0f / D) - mean * mean;
    float r = 1.0f / sqrtf(var + LN_EPS);

    const float4* wr = (const float4*)w;
    const float4* br = (const float4*)b;
    float4 w0 = wr[tid], w1 = wr[tid + 256];
    float4 b0 = br[tid], b1 = br[tid + 256];
    float4 o0, o1;
    o0.x = (v0.x - mean) * r * w0.x + b0.x;
    o0.y = (v0.y - mean) * r * w0.y + b0.y;
    o0.z = (v0.z - mean) * r * w0.z + b0.z;
    o0.w = (v0.w - mean) * r * w0.w + b0.w;
    o1.x = (v1.x - mean) * r * w1.x + b1.x;
    o1.y = (v1.y - mean) * r * w1.y + b1.y;
    o1.z = (v1.z - mean) * r * w1.z + b1.z;
    o1.w = (v1.w - mean) * r * w1.w + b1.w;
    float4* outr = (float4*)(g_normed + (size_t)row * D);
    outr[tid] = o0;
    outr[tid + 256] = o1;

    __nv_bfloat16* arow = g_A2 + (size_t)row * (2 * D);
    uint2 h0, l0, h1, l1;
    split4(o0, h0, l0);
    split4(o1, h1, l1);
    ((uint2*)arow)[tid]             = h0;
    ((uint2*)arow)[tid + 256]       = h1;
    ((uint2*)(arow + D))[tid]       = l0;
    ((uint2*)(arow + D))[tid + 256] = l1;
}

// ---------------- weight convert: W2 = [hi | lo] ----------------------------
__global__ __launch_bounds__(256) void conv_w_kernel(const float* __restrict__ wq,
                                                     const float* __restrict__ wk,
                                                     const float* __restrict__ wv) {
    int j = blockIdx.x;                    // weight row (output feature)
    int wsel = blockIdx.y;                 // 0..2
    const float* W = (wsel == 0) ? wq : (wsel == 1) ? wk : wv;
    __nv_bfloat16* dst = g_W2 + (size_t)wsel * ((size_t)D * 2 * D) + (size_t)j * (2 * D);
    const float4* src = (const float4*)(W + (size_t)j * D);
    int tid = threadIdx.x;
    #pragma unroll
    for (int h = 0; h < 2; h++) {
        float4 v = src[tid + h * 256];
        uint2 hi, lo;
        split4(v, hi, lo);
        ((uint2*)dst)[tid + h * 256] = hi;
        ((uint2*)(dst + D))[tid + h * 256] = lo;
    }
}

// ---------------- QKV GEMM via mma.sync (bf16, split precision) -------------
// C[4096, 2048] = A2 @ W2^T over logical K'=6144 (hh + hl + lh)
// grid (8 N-tiles, 32 M-tiles, 3), 256 threads, warp tile 64x64, 4-stage pipe
__global__ __launch_bounds__(256, 1) void qkv_mma_kernel(const float* __restrict__ bq,
                                                         const float* __restrict__ bk,
                                                         const float* __restrict__ bv) {
    extern __shared__ __align__(128) char sm[];
    uint32_t sbase = smem_u32(sm);

    int tid = threadIdx.x;
    int lane = tid & 31;
    int wid = tid >> 5;
    int warp_m = wid >> 2;        // 0..1  -> 64-row slab
    int warp_n = wid & 3;         // 0..3  -> 64-col slab
    int bx = blockIdx.x;          // N tile
    int by = blockIdx.y;          // M tile
    int bz = blockIdx.z;          // q/k/v

    const float* bias = (bz == 0) ? bq : (bz == 1) ? bk : bv;
    float* C = (bz == 0) ? g_q : (bz == 1) ? g_k : g_v;
    const char* Abase = (const char*)g_A2;
    const char* Bbase = (const char*)(g_W2 + (size_t)bz * ((size_t)D * 2 * D));

    auto load_stage = [&](int st, int j) {
        int jj = j & 31;                                   // 0..31 within segment
        size_t koffA = (size_t)jj * 128 + ((j >= 64) ? 4096u : 0u);          // lh: A-lo
        size_t koffB = (size_t)jj * 128 + ((j >= 32 && j < 64) ? 4096u : 0u); // hl: B-lo
        uint32_t sA = sbase + st * GSTAGE_BYTES;
        uint32_t sB = sA + 16384;
        #pragma unroll
        for (int i = 0; i < 4; i++) {                      // A: 128 rows x 128B
            int idx = tid + i * 256;
            int row = idx >> 3;
            int c16 = idx & 7;
            uint32_t dst = sA + row * 128 + ((c16 ^ (row & 7)) << 4);
            cp16(dst, Abase + (size_t)(by * GBM + row) * 8192 + koffA + c16 * 16);
        }
        #pragma unroll
        for (int i = 0; i < 8; i++) {                      // B: 256 rows x 128B
            int idx = tid + i * 256;
            int row = idx >> 3;
            int c16 = idx & 7;
            uint32_t dst = sB + row * 128 + ((c16 ^ (row & 7)) << 4);
            cp16(dst, Bbase + (size_t)(bx * GBN + row) * 8192 + koffB + c16 * 16);
        }
    };

    float acc[4][8][4];
    #pragma unroll
    for (int mf = 0; mf < 4; mf++)
        #pragma unroll
        for (int nf = 0; nf < 8; nf++)
            #pragma unroll
            for (int q = 0; q < 4; q++) acc[mf][nf][q] = 0.f;

    // prologue: stages 0 and 1
    load_stage(0, 0);
    cp_commit();
    load_stage(1, 1);
    cp_commit();

    int arow_off = warp_m * 64 + (lane & 15);
    int brow_off = warp_n * 64 + (lane & 15);
    int khalf = lane >> 4;
    int swz_x = lane & 7;

    for (int it = 0; it < KITERS; it++) {
        if (it + 2 < KITERS) load_stage((it + 2) & 3, it + 2);
        cp_commit();
        cp_wait<2>();
        __syncthreads();

        uint32_t sA = sbase + (it & 3) * GSTAGE_BYTES;
        uint32_t sB = sA + 16384;

        #pragma unroll
        for (int ks = 0; ks < 4; ks++) {
            uint32_t swz = (uint32_t)(((ks * 2 + khalf) ^ swz_x) << 4);
            uint32_t a[4][4];
            uint32_t bf[8][2];
            #pragma unroll
            for (int mf = 0; mf < 4; mf++) {
                uint32_t addr = sA + (uint32_t)(arow_off + mf * 16) * 128 + swz;
                LDSM4(a[mf][0], a[mf][1], a[mf][2], a[mf][3], addr);
            }
            #pragma unroll
            for (int nf2 = 0; nf2 < 4; nf2++) {
                uint32_t r0, r1, r2, r3;
                uint32_t addr = sB + (uint32_t)(brow_off + nf2 * 16) * 128 + swz;
                LDSM4(r0, r1, r2, r3, addr);
                bf[nf2 * 2 + 0][0] = r0; bf[nf2 * 2 + 1][0] = r1;
                bf[nf2 * 2 + 0][1] = r2; bf[nf2 * 2 + 1][1] = r3;
            }
            #pragma unroll
            for (int mf = 0; mf < 4; mf++)
                #pragma unroll
                for (int nf = 0; nf < 8; nf++)
                    asm volatile(
                        "mma.sync.aligned.m16n8k16.row.col.f32.bf16.bf16.f32 "
                        "{%0,%1,%2,%3}, {%4,%5,%6,%7}, {%8,%9}, {%0,%1,%2,%3};"
                        : "+f"(acc[mf][nf][0]), "+f"(acc[mf][nf][1]),
                          "+f"(acc[mf][nf][2]), "+f"(acc[mf][nf][3])
                        : "r"(a[mf][0]), "r"(a[mf][1]), "r"(a[mf][2]), "r"(a[mf][3]),
                          "r"(bf[nf][0]), "r"(bf[nf][1]));
        }
    }

    // epilogue: direct stores with bias
    int row_base = by * GBM + warp_m * 64 + (lane >> 2);
    int col_base = bx * GBN + warp_n * 64 + 2 * (lane & 3);
    #pragma unroll
    for (int nf = 0; nf < 8; nf++) {
        int c = col_base + nf * 8;
        float b0 = bias[c], b1 = bias[c + 1];
        #pragma unroll
        for (int mf = 0; mf < 4; mf++) {
            int r0 = row_base + mf * 16;
            float2 v0 = make_float2(acc[mf][nf][0] + b0, acc[mf][nf][1] + b1);
            float2 v1 = make_float2(acc[mf][nf][2] + b0, acc[mf][nf][3] + b1);
            *(float2*)(C + (size_t)r0 * D + c) = v0;
            *(float2*)(C + (size_t)(r0 + 8) * D + c) = v1;
        }
    }
}

// ---------------- scores partial: S_part[ks][b] = q.k over K chunk ----------
__global__ __launch_bounds__(256) void scores_kernel() {
    int ks = blockIdx.x;            // 0..3 k-split
    int b = blockIdx.y;             // batch
    const float* Qb = g_q + (size_t)b * NA * D + (size_t)ks * SCORE_KCHUNK;
    const float* Kb = g_k + (size_t)b * NA * D + (size_t)ks * SCORE_KCHUNK;
    __shared__ float Qs[32][68];
    __shared__ float Ks[32][68];
    int tid = threadIdx.x;
    int lr = tid >> 3;
    int lk = (tid & 7) << 2;
    int tm = tid >> 4, tn = tid & 15;
    float acc[4][4];
    #pragma unroll
    for (int i = 0; i < 4; i++)
        #pragma unroll
        for (int j = 0; j < 4; j++) acc[i][j] = 0.f;

    for (int k0 = 0; k0 < SCORE_KCHUNK; k0 += 32) {
        float4 q0 = *(const float4*)(Qb + (size_t)lr * D + k0 + lk);
        float4 q1 = *(const float4*)(Qb + (size_t)(lr + 32) * D + k0 + lk);
        float4 c0 = *(const float4*)(Kb + (size_t)lr * D + k0 + lk);
        float4 c1 = *(const float4*)(Kb + (size_t)(lr + 32) * D + k0 + lk);
        __syncthreads();
        Qs[lk + 0][lr] = q0.x; Qs[lk + 1][lr] = q0.y; Qs[lk + 2][lr] = q0.z; Qs[lk + 3][lr] = q0.w;
        Qs[lk + 0][lr + 32] = q1.x; Qs[lk + 1][lr + 32] = q1.y; Qs[lk + 2][lr + 32] = q1.z; Qs[lk + 3][lr + 32] = q1.w;
        Ks[lk + 0][lr] = c0.x; Ks[lk + 1][lr] = c0.y; Ks[lk + 2][lr] = c0.z; Ks[lk + 3][lr] = c0.w;
        Ks[lk + 0][lr + 32] = c1.x; Ks[lk + 1][lr + 32] = c1.y; Ks[lk + 2][lr + 32] = c1.z; Ks[lk + 3][lr + 32] = c1.w;
        __syncthreads();
        #pragma unroll
        for (int kk = 0; kk < 32; kk++) {
            float a[4], c[4];
            *(float4*)a = *(const float4*)(&Qs[kk][tm * 4]);
            *(float4*)c = *(const float4*)(&Ks[kk][tn * 4]);
            #pragma unroll
            for (int i = 0; i < 4; i++)
                #pragma unroll
                for (int j = 0; j < 4; j++)
                    acc[i][j] += a[i] * c[j];
        }
    }
    float* dst = g_spart + ((size_t)ks * BATCH + b) * 4096;
    #pragma unroll
    for (int i = 0; i < 4; i++)
        #pragma unroll
        for (int j = 0; j < 4; j++)
            dst[(tm * 4 + i) * 64 + (tn * 4 + j)] = acc[i][j];
}

// ---------------- Sinkhorn (sums partials, applies 1/sqrt(D)) ---------------
__global__ __launch_bounds__(1024) void sinkhorn_kernel(float* __restrict__ attn_out) {
    int b = blockIdx.x;
    __shared__ float m[64][65];
    int tid = threadIdx.x;
    const float invS = 1.0f / 45.254833995939045f;  // 1/(sqrt(2048)*TEMP)
    const float* p0 = g_spart + (size_t)b * 4096;
    const size_t pstride = (size_t)BATCH * 4096;
    for (int i = tid; i < 4096; i += 1024) {
        float v = p0[i] + p0[i + pstride] + p0[i + 2 * pstride] + p0[i + 3 * pstride];
        m[i >> 6][i & 63] = v * invS;
    }
    __syncthreads();
    int w = tid >> 5, lane = tid & 31;
    for (int it = 0; it < SINKHORN_ITERS; it++) {
        #pragma unroll
        for (int rr = 0; rr < 2; rr++) {
            int r = w * 2 + rr;
            float x0 = m[r][lane], x1 = m[r][lane + 32];
            float mx = fmaxf(x0, x1);
            #pragma unroll
            for (int o = 16; o; o >>= 1) mx = fmaxf(mx, __shfl_xor_sync(0xFFFFFFFFu, mx, o));
            float s = expf(x0 - mx) + expf(x1 - mx);
            #pragma unroll
            for (int o = 16; o; o >>= 1) s += __shfl_xor_sync(0xFFFFFFFFu, s, o);
            float lse = mx + logf(s);
            m[r][lane] = x0 - lse;
            m[r][lane + 32] = x1 - lse;
        }
        __syncthreads();
        #pragma unroll
        for (int cc = 0; cc < 2; cc++) {
            int c = w * 2 + cc;
            float x0 = m[lane][c], x1 = m[lane + 32][c];
            float mx = fmaxf(x0, x1);
            #pragma unroll
            for (int o = 16; o; o >>= 1) mx = fmaxf(mx, __shfl_xor_sync(0xFFFFFFFFu, mx, o));
            float s = expf(x0 - mx) + expf(x1 - mx);
            #pragma unroll
            for (int o = 16; o; o >>= 1) s += __shfl_xor_sync(0xFFFFFFFFu, s, o);
            float lse = mx + logf(s);
            m[lane][c] = x0 - lse;
            m[lane + 32][c] = x1 - lse;
        }
        __syncthreads();
    }
    for (int i = tid; i < 4096; i += 1024) {
        float e = expf(m[i >> 6][i & 63]);
        g_attn[(size_t)b * 4096 + i] = e;
        if (attn_out) attn_out[(size_t)b * 4096 + i] = e;
    }
}

// ---------------- attended = attn @ V, fused mix ----------------------------
__global__ __launch_bounds__(256) void attended_kernel() {
    int d0 = blockIdx.x * 128;
    int b = blockIdx.y;
    __shared__ float attn_s[64][64];
    __shared__ float4 Vs[64][32];
    int tid = threadIdx.x;
    const float* ab = g_attn + (size_t)b * 4096;
    for (int i = tid; i < 4096; i += 256) attn_s[i >> 6][i & 63] = ab[i];
    const float* Vb = g_v + (size_t)b * NA * D;
    {
        int r = tid >> 5;
        int c = tid & 31;
        #pragma unroll
        for (int p = 0; p < 8; p++)
            Vs[r + p * 8][c] = *(const float4*)(Vb + (size_t)(r + p * 8) * D + d0 + c * 4);
    }
    __syncthreads();
    int tx = tid & 31, ty = tid >> 5;
    float4 acc[8];
    #pragma unroll
    for (int i = 0; i < 8; i++) acc[i] = make_float4(0.f, 0.f, 0.f, 0.f);
    for (int mm = 0; mm < 64; mm++) {
        float4 v4 = Vs[mm][tx];
        #pragma unroll
        for (int i = 0; i < 8; i++) {
            float a = attn_s[ty * 8 + i][mm];
            acc[i].x += a * v4.x;
            acc[i].y += a * v4.y;
            acc[i].z += a * v4.z;
            acc[i].w += a * v4.w;
        }
    }
    #pragma unroll
    for (int i = 0; i < 8; i++) {
        int n = ty * 8 + i;
        size_t off = ((size_t)(b * 64 + n)) * D + d0 + tx * 4;
        float4 nm = *(const float4*)(g_normed + off);
        float4 o;
        o.x = ID_PRESERVE * nm.x + (1.0f - ID_PRESERVE) * acc[i].x;
        o.y = ID_PRESERVE * nm.y + (1.0f - ID_PRESERVE) * acc[i].y;
        o.z = ID_PRESERVE * nm.z + (1.0f - ID_PRESERVE) * acc[i].z;
        o.w = ID_PRESERVE * nm.w + (1.0f - ID_PRESERVE) * acc[i].w;
        *(float4*)(g_mixed + off) = o;
    }
}

// ---------------- epilogue ---------------------------------------------------
__global__ __launch_bounds__(256) void epilogue_kernel(const float* __restrict__ x,
                                                       const float* __restrict__ biases,
                                                       const float* __restrict__ scales,
                                                       float* __restrict__ out) {
    __shared__ float red[8];
    int row = blockIdx.x;
    int n = row & 63;
    int tid = threadIdx.x;
    float sc = scales[n];
    const float4* mr = (const float4*)(g_mixed + (size_t)row * D);
    const float4* br = (const float4*)(biases + (size_t)n * D);
    float4 m0 = mr[tid], m1 = mr[tid + 256];
    float4 b0 = br[tid], b1 = br[tid + 256];
    float4 s0, s1;
    s0.x = (m0.x + b0.x) * sc; s0.y = (m0.y + b0.y) * sc;
    s0.z = (m0.z + b0.z) * sc; s0.w = (m0.w + b0.w) * sc;
    s1.x = (m1.x + b1.x) * sc; s1.y = (m1.y + b1.y) * sc;
    s1.z = (m1.z + b1.z) * sc; s1.w = (m1.w + b1.w) * sc;
    float ss = s0.x*s0.x + s0.y*s0.y + s0.z*s0.z + s0.w*s0.w
             + s1.x*s1.x + s1.y*s1.y + s1.z*s1.z + s1.w*s1.w;
    #pragma unroll
    for (int o = 16; o; o >>= 1) ss += __shfl_xor_sync(0xFFFFFFFFu, ss, o);
    if ((tid & 31) == 0) red[tid >> 5] = ss;
    __syncthreads();
    float tot = 0.f;
    #pragma unroll
    for (int i = 0; i < 8; i++) tot += red[i];
    float norm = sqrtf(tot);
    float inv = 1.0f / fmaxf(1.0f, norm / SIGNAL_BOUND);
    const float4* xr = (const float4*)(x + (size_t)row * D);
    float4 x0 = xr[tid], x1 = xr[tid + 256];
    float4 o0, o1;
    o0.x = x0.x + s0.x * inv; o0.y = x0.y + s0.y * inv;
    o0.z = x0.z + s0.z * inv; o0.w = x0.w + s0.w * inv;
    o1.x = x1.x + s1.x * inv; o1.y = x1.y + s1.y * inv;
    o1.z = x1.z + s1.z * inv; o1.w = x1.w + s1.w * inv;
    float4* outr = (float4*)(out + (size_t)row * D);
    outr[tid] = o0;
    outr[tid + 256] = o1;
}

// ---------------- launch -----------------------------------------------------
extern "C" void kernel_launch(void* const* d_in, const int* in_sizes, int n_in,
                              void* d_out, int out_size) {
    const float* agent_states  = (const float*)d_in[0];
    const float* ln_w          = (const float*)d_in[1];
    const float* ln_b          = (const float*)d_in[2];
    const float* wq            = (const float*)d_in[3];
    const float* bq            = (const float*)d_in[4];
    const float* wk            = (const float*)d_in[5];
    const float* bk            = (const float*)d_in[6];
    const float* wv            = (const float*)d_in[7];
    const float* bv            = (const float*)d_in[8];
    const float* agent_biases  = (const float*)d_in[9];
    const float* scale_factors = (const float*)d_in[10];
    float* out = (float*)d_out;
    float* attn_out = (out_size >= ROWS * D + BATCH * NA * NA) ? (out + (size_t)ROWS * D)
                                                               : nullptr;

    const int DYN_SMEM = GSTAGES * GSTAGE_BYTES;   // 192 KB
    cudaFuncSetAttribute(qkv_mma_kernel, cudaFuncAttributeMaxDynamicSharedMemorySize, DYN_SMEM);

    ln_kernel<<<ROWS, 256>>>(agent_states, ln_w, ln_b);
    conv_w_kernel<<<dim3(D, 3), 256>>>(wq, wk, wv);
    qkv_mma_kernel<<<dim3(D / GBN, ROWS / GBM, 3), 256, DYN_SMEM>>>(bq, bk, bv);
    scores_kernel<<<dim3(SCORE_KSPLIT, BATCH), 256>>>();
    sinkhorn_kernel<<<BATCH, 1024>>>(attn_out);
    attended_kernel<<<dim3(16, BATCH), 256>>>();
    epilogue_kernel<<<ROWS, 256>>>(agent_states, agent_biases, scale_factors, out);
}

// round 6
// speedup vs baseline: 1.0874x; 1.0874x over previous
#include <cuda_runtime.h>
#include <cuda_bf16.h>
#include <math.h>
#include <stdint.h>

#define D 2048
#define NA 64
#define BATCH 64
#define ROWS (BATCH * NA)        // 4096
#define LN_EPS 1e-5f
#define ID_PRESERVE 0.1f
#define SIGNAL_BOUND 1.0f
#define SINKHORN_ITERS 50

// GEMM config (R4-proven): CTA 128x128, BK=64 bf16 (128B rows), 3-stage cp.async
#define GBM 128
#define GBN 128
#define KITERS 96                // 3 * 2048 / 64  (hh, hl, lh)
#define GSTAGES 3
#define GSTAGE_BYTES 32768       // A 16KB + B 16KB

#define SCORE_KSPLIT 4
#define SCORE_KCHUNK (D / SCORE_KSPLIT)   // 512

// ---------------- scratch (device globals; no allocation allowed) ----------
__device__ float g_normed[ROWS * D];
__device__ float g_q[ROWS * D];
__device__ float g_k[ROWS * D];
__device__ float g_v[ROWS * D];
__device__ float g_mixed[ROWS * D];
__device__ float g_spart[SCORE_KSPLIT * BATCH * NA * NA];
__device__ float g_attn[BATCH * NA * NA];
// split-bf16 operands: [hi(2048) | lo(2048)] along K per row
__device__ __nv_bfloat16 g_A2[(size_t)ROWS * 2 * D];           // [4096, 4096]
__device__ __nv_bfloat16 g_W2[3ull * D * 2 * D];               // 3 x [2048, 4096]

// ---------------- PTX helpers (sm_100 baseline only) -------------------------
__device__ __forceinline__ uint32_t smem_u32(const void* p) {
    uint32_t a;
    asm("{ .reg .u64 t; cvta.to.shared.u64 t, %1; cvt.u32.u64 %0, t; }" : "=r"(a) : "l"(p));
    return a;
}
__device__ __forceinline__ void cp16(uint32_t dst, const void* src) {
    asm volatile("cp.async.cg.shared.global [%0], [%1], 16;" :: "r"(dst), "l"(src));
}
__device__ __forceinline__ void cp_commit() { asm volatile("cp.async.commit_group;" ::: "memory"); }
template <int N>
__device__ __forceinline__ void cp_wait() { asm volatile("cp.async.wait_group %0;" :: "n"(N) : "memory"); }

#define LDSM4(r0, r1, r2, r3, addr) \
    asm volatile("ldmatrix.sync.aligned.m8n8.x4.shared.b16 {%0,%1,%2,%3}, [%4];" \
                 : "=r"(r0), "=r"(r1), "=r"(r2), "=r"(r3) : "r"(addr))

// ---------------- fp32 -> (hi, lo) bf16 split --------------------------------
__device__ __forceinline__ void split4(float4 v, uint2& hi, uint2& lo) {
    __nv_bfloat16 hx = __float2bfloat16(v.x);
    __nv_bfloat16 hy = __float2bfloat16(v.y);
    __nv_bfloat16 hz = __float2bfloat16(v.z);
    __nv_bfloat16 hw = __float2bfloat16(v.w);
    __nv_bfloat16 lx = __float2bfloat16(v.x - __bfloat162float(hx));
    __nv_bfloat16 ly = __float2bfloat16(v.y - __bfloat162float(hy));
    __nv_bfloat16 lz = __float2bfloat16(v.z - __bfloat162float(hz));
    __nv_bfloat16 lw = __float2bfloat16(v.w - __bfloat162float(hw));
    union { __nv_bfloat16 h[4]; uint2 u; } a, b;
    a.h[0] = hx; a.h[1] = hy; a.h[2] = hz; a.h[3] = hw;
    b.h[0] = lx; b.h[1] = ly; b.h[2] = lz; b.h[3] = lw;
    hi = a.u; lo = b.u;
}

// ---------------- LayerNorm + emit bf16 split --------------------------------
__global__ __launch_bounds__(256) void ln_kernel(const float* __restrict__ x,
                                                 const float* __restrict__ w,
                                                 const float* __restrict__ b) {
    __shared__ float redS[8], redQ[8];
    int row = blockIdx.x;
    int tid = threadIdx.x;
    const float4* xr = (const float4*)(x + (size_t)row * D);
    float4 v0 = xr[tid];
    float4 v1 = xr[tid + 256];
    float s  = v0.x + v0.y + v0.z + v0.w + v1.x + v1.y + v1.z + v1.w;
    float ss = v0.x*v0.x + v0.y*v0.y + v0.z*v0.z + v0.w*v0.w
             + v1.x*v1.x + v1.y*v1.y + v1.z*v1.z + v1.w*v1.w;
    #pragma unroll
    for (int o = 16; o; o >>= 1) {
        s  += __shfl_xor_sync(0xFFFFFFFFu, s, o);
        ss += __shfl_xor_sync(0xFFFFFFFFu, ss, o);
    }
    int wid = tid >> 5;
    if ((tid & 31) == 0) { redS[wid] = s; redQ[wid] = ss; }
    __syncthreads();
    float ts = 0.f, tq = 0.f;
    #pragma unroll
    for (int i = 0; i < 8; i++) { ts += redS[i]; tq += redQ[i]; }
    float mean = ts * (1.0f / D);
    float var  = tq * (1.0f / D) - mean * mean;
    float r = 1.0f / sqrtf(var + LN_EPS);

    const float4* wr = (const float4*)w;
    const float4* br = (const float4*)b;
    float4 w0 = wr[tid], w1 = wr[tid + 256];
    float4 b0 = br[tid], b1 = br[tid + 256];
    float4 o0, o1;
    o0.x = (v0.x - mean) * r * w0.x + b0.x;
    o0.y = (v0.y - mean) * r * w0.y + b0.y;
    o0.z = (v0.z - mean) * r * w0.z + b0.z;
    o0.w = (v0.w - mean) * r * w0.w + b0.w;
    o1.x = (v1.x - mean) * r * w1.x + b1.x;
    o1.y = (v1.y - mean) * r * w1.y + b1.y;
    o1.z = (v1.z - mean) * r * w1.z + b1.z;
    o1.w = (v1.w - mean) * r * w1.w + b1.w;
    float4* outr = (float4*)(g_normed + (size_t)row * D);
    outr[tid] = o0;
    outr[tid + 256] = o1;

    __nv_bfloat16* arow = g_A2 + (size_t)row * (2 * D);
    uint2 h0, l0, h1, l1;
    split4(o0, h0, l0);
    split4(o1, h1, l1);
    ((uint2*)arow)[tid]             = h0;
    ((uint2*)arow)[tid + 256]       = h1;
    ((uint2*)(arow + D))[tid]       = l0;
    ((uint2*)(arow + D))[tid + 256] = l1;
}

// ---------------- weight convert: W2 = [hi | lo] ----------------------------
__global__ __launch_bounds__(256) void conv_w_kernel(const float* __restrict__ wq,
                                                     const float* __restrict__ wk,
                                                     const float* __restrict__ wv) {
    int j = blockIdx.x;                    // weight row (output feature)
    int wsel = blockIdx.y;                 // 0..2
    const float* W = (wsel == 0) ? wq : (wsel == 1) ? wk : wv;
    __nv_bfloat16* dst = g_W2 + (size_t)wsel * ((size_t)D * 2 * D) + (size_t)j * (2 * D);
    const float4* src = (const float4*)(W + (size_t)j * D);
    int tid = threadIdx.x;
    #pragma unroll
    for (int h = 0; h < 2; h++) {
        float4 v = src[tid + h * 256];
        uint2 hi, lo;
        split4(v, hi, lo);
        ((uint2*)dst)[tid + h * 256] = hi;
        ((uint2*)(dst + D))[tid + h * 256] = lo;
    }
}

// ---------------- QKV GEMM via mma.sync (bf16, split precision) -------------
// C[4096, 2048] = A2 @ W2^T over logical K'=6144 (hh + hl + lh)
// grid (16 N-tiles, 32 M-tiles, 3), 256 threads, warp tile 64x32 (R4-proven)
__global__ __launch_bounds__(256, 2) void qkv_mma_kernel(const float* __restrict__ bq,
                                                         const float* __restrict__ bk,
                                                         const float* __restrict__ bv) {
    extern __shared__ __align__(128) char sm[];
    uint32_t sbase = smem_u32(sm);

    int tid = threadIdx.x;
    int lane = tid & 31;
    int wid = tid >> 5;
    int warp_m = wid >> 2;        // 0..1  -> 64-row slab
    int warp_n = wid & 3;         // 0..3  -> 32-col slab
    int bx = blockIdx.x;          // N tile
    int by = blockIdx.y;          // M tile
    int bz = blockIdx.z;          // q/k/v

    const float* bias = (bz == 0) ? bq : (bz == 1) ? bk : bv;
    float* C = (bz == 0) ? g_q : (bz == 1) ? g_k : g_v;
    const char* Abase = (const char*)g_A2;
    const char* Bbase = (const char*)(g_W2 + (size_t)bz * ((size_t)D * 2 * D));

    auto load_stage = [&](int st, int j) {
        int jj = j & 31;                                   // 0..31 within segment
        size_t koffA = (size_t)jj * 128 + ((j >= 64) ? 4096u : 0u);          // lh: A-lo
        size_t koffB = (size_t)jj * 128 + ((j >= 32 && j < 64) ? 4096u : 0u); // hl: B-lo
        uint32_t sA = sbase + st * GSTAGE_BYTES;
        uint32_t sB = sA + 16384;
        #pragma unroll
        for (int i = 0; i < 4; i++) {
            int idx = tid + i * 256;
            int row = idx >> 3;
            int c16 = idx & 7;
            uint32_t dst = sA + row * 128 + ((c16 ^ (row & 7)) << 4);
            cp16(dst, Abase + (size_t)(by * GBM + row) * 8192 + koffA + c16 * 16);
        }
        #pragma unroll
        for (int i = 0; i < 4; i++) {
            int idx = tid + i * 256;
            int row = idx >> 3;
            int c16 = idx & 7;
            uint32_t dst = sB + row * 128 + ((c16 ^ (row & 7)) << 4);
            cp16(dst, Bbase + (size_t)(bx * GBN + row) * 8192 + koffB + c16 * 16);
        }
    };

    float acc[4][4][4];
    #pragma unroll
    for (int mf = 0; mf < 4; mf++)
        #pragma unroll
        for (int nf = 0; nf < 4; nf++)
            #pragma unroll
            for (int q = 0; q < 4; q++) acc[mf][nf][q] = 0.f;

    // prologue: stages 0 and 1
    load_stage(0, 0);
    cp_commit();
    load_stage(1, 1);
    cp_commit();

    int arow_off = warp_m * 64 + (lane & 15);   // A ldmatrix row base (per mf +16)
    int brow_off = warp_n * 32 + (lane & 15);   // B ldmatrix row base (per nf2 +16)
    int khalf = lane >> 4;                      // 0/1: which k-half this lane addresses
    int swz_x = lane & 7;

    for (int it = 0; it < KITERS; it++) {
        cp_wait<1>();
        __syncthreads();
        if (it + 2 < KITERS) load_stage((it + 2) % GSTAGES, it + 2);
        cp_commit();

        uint32_t sA = sbase + (it % GSTAGES) * GSTAGE_BYTES;
        uint32_t sB = sA + 16384;

        #pragma unroll
        for (int ks = 0; ks < 4; ks++) {
            uint32_t swz = (uint32_t)(((ks * 2 + khalf) ^ swz_x) << 4);
            uint32_t a[4][4];
            uint32_t bf[4][2];
            #pragma unroll
            for (int mf = 0; mf < 4; mf++) {
                uint32_t addr = sA + (uint32_t)(arow_off + mf * 16) * 128 + swz;
                LDSM4(a[mf][0], a[mf][1], a[mf][2], a[mf][3], addr);
            }
            #pragma unroll
            for (int nf2 = 0; nf2 < 2; nf2++) {
                uint32_t r0, r1, r2, r3;
                uint32_t addr = sB + (uint32_t)(brow_off + nf2 * 16) * 128 + swz;
                LDSM4(r0, r1, r2, r3, addr);
                bf[nf2 * 2 + 0][0] = r0; bf[nf2 * 2 + 1][0] = r1;
                bf[nf2 * 2 + 0][1] = r2; bf[nf2 * 2 + 1][1] = r3;
            }
            #pragma unroll
            for (int mf = 0; mf < 4; mf++)
                #pragma unroll
                for (int nf = 0; nf < 4; nf++)
                    asm volatile(
                        "mma.sync.aligned.m16n8k16.row.col.f32.bf16.bf16.f32 "
                        "{%0,%1,%2,%3}, {%4,%5,%6,%7}, {%8,%9}, {%0,%1,%2,%3};"
                        : "+f"(acc[mf][nf][0]), "+f"(acc[mf][nf][1]),
                          "+f"(acc[mf][nf][2]), "+f"(acc[mf][nf][3])
                        : "r"(a[mf][0]), "r"(a[mf][1]), "r"(a[mf][2]), "r"(a[mf][3]),
                          "r"(bf[nf][0]), "r"(bf[nf][1]));
        }
        __syncthreads();
    }

    // epilogue: direct stores with bias
    int row_base = by * GBM + warp_m * 64 + (lane >> 2);
    int col_base = bx * GBN + warp_n * 32 + 2 * (lane & 3);
    #pragma unroll
    for (int nf = 0; nf < 4; nf++) {
        int c = col_base + nf * 8;
        float b0 = bias[c], b1 = bias[c + 1];
        #pragma unroll
        for (int mf = 0; mf < 4; mf++) {
            int r0 = row_base + mf * 16;
            float2 v0 = make_float2(acc[mf][nf][0] + b0, acc[mf][nf][1] + b1);
            float2 v1 = make_float2(acc[mf][nf][2] + b0, acc[mf][nf][3] + b1);
            *(float2*)(C + (size_t)r0 * D + c) = v0;
            *(float2*)(C + (size_t)(r0 + 8) * D + c) = v1;
        }
    }
}

// ---------------- scores partial: S_part[ks][b] = q.k over K chunk ----------
__global__ __launch_bounds__(256) void scores_kernel() {
    int ks = blockIdx.x;            // 0..3 k-split
    int b = blockIdx.y;             // batch
    const float* Qb = g_q + (size_t)b * NA * D + (size_t)ks * SCORE_KCHUNK;
    const float* Kb = g_k + (size_t)b * NA * D + (size_t)ks * SCORE_KCHUNK;
    __shared__ float Qs[32][68];
    __shared__ float Ks[32][68];
    int tid = threadIdx.x;
    int lr = tid >> 3;
    int lk = (tid & 7) << 2;
    int tm = tid >> 4, tn = tid & 15;
    float acc[4][4];
    #pragma unroll
    for (int i = 0; i < 4; i++)
        #pragma unroll
        for (int j = 0; j < 4; j++) acc[i][j] = 0.f;

    for (int k0 = 0; k0 < SCORE_KCHUNK; k0 += 32) {
        float4 q0 = *(const float4*)(Qb + (size_t)lr * D + k0 + lk);
        float4 q1 = *(const float4*)(Qb + (size_t)(lr + 32) * D + k0 + lk);
        float4 c0 = *(const float4*)(Kb + (size_t)lr * D + k0 + lk);
        float4 c1 = *(const float4*)(Kb + (size_t)(lr + 32) * D + k0 + lk);
        __syncthreads();
        Qs[lk + 0][lr] = q0.x; Qs[lk + 1][lr] = q0.y; Qs[lk + 2][lr] = q0.z; Qs[lk + 3][lr] = q0.w;
        Qs[lk + 0][lr + 32] = q1.x; Qs[lk + 1][lr + 32] = q1.y; Qs[lk + 2][lr + 32] = q1.z; Qs[lk + 3][lr + 32] = q1.w;
        Ks[lk + 0][lr] = c0.x; Ks[lk + 1][lr] = c0.y; Ks[lk + 2][lr] = c0.z; Ks[lk + 3][lr] = c0.w;
        Ks[lk + 0][lr + 32] = c1.x; Ks[lk + 1][lr + 32] = c1.y; Ks[lk + 2][lr + 32] = c1.z; Ks[lk + 3][lr + 32] = c1.w;
        __syncthreads();
        #pragma unroll
        for (int kk = 0; kk < 32; kk++) {
            float a[4], c[4];
            *(float4*)a = *(const float4*)(&Qs[kk][tm * 4]);
            *(float4*)c = *(const float4*)(&Ks[kk][tn * 4]);
            #pragma unroll
            for (int i = 0; i < 4; i++)
                #pragma unroll
                for (int j = 0; j < 4; j++)
                    acc[i][j] += a[i] * c[j];
        }
    }
    float* dst = g_spart + ((size_t)ks * BATCH + b) * 4096;
    #pragma unroll
    for (int i = 0; i < 4; i++)
        #pragma unroll
        for (int j = 0; j < 4; j++)
            dst[(tm * 4 + i) * 64 + (tn * 4 + j)] = acc[i][j];
}

// ---------------- Sinkhorn (sums partials, applies 1/sqrt(D)) ---------------
__global__ __launch_bounds__(1024) void sinkhorn_kernel(float* __restrict__ attn_out) {
    int b = blockIdx.x;
    __shared__ float m[64][65];
    int tid = threadIdx.x;
    const float invS = 1.0f / 45.254833995939045f;  // 1/(sqrt(2048)*TEMP)
    const float* p0 = g_spart + (size_t)b * 4096;
    const size_t pstride = (size_t)BATCH * 4096;
    for (int i = tid; i < 4096; i += 1024) {
        float v = p0[i] + p0[i + pstride] + p0[i + 2 * pstride] + p0[i + 3 * pstride];
        m[i >> 6][i & 63] = v * invS;
    }
    __syncthreads();
    int w = tid >> 5, lane = tid & 31;
    for (int it = 0; it < SINKHORN_ITERS; it++) {
        #pragma unroll
        for (int rr = 0; rr < 2; rr++) {
            int r = w * 2 + rr;
            float x0 = m[r][lane], x1 = m[r][lane + 32];
            float mx = fmaxf(x0, x1);
            #pragma unroll
            for (int o = 16; o; o >>= 1) mx = fmaxf(mx, __shfl_xor_sync(0xFFFFFFFFu, mx, o));
            float s = expf(x0 - mx) + expf(x1 - mx);
            #pragma unroll
            for (int o = 16; o; o >>= 1) s += __shfl_xor_sync(0xFFFFFFFFu, s, o);
            float lse = mx + logf(s);
            m[r][lane] = x0 - lse;
            m[r][lane + 32] = x1 - lse;
        }
        __syncthreads();
        #pragma unroll
        for (int cc = 0; cc < 2; cc++) {
            int c = w * 2 + cc;
            float x0 = m[lane][c], x1 = m[lane + 32][c];
            float mx = fmaxf(x0, x1);
            #pragma unroll
            for (int o = 16; o; o >>= 1) mx = fmaxf(mx, __shfl_xor_sync(0xFFFFFFFFu, mx, o));
            float s = expf(x0 - mx) + expf(x1 - mx);
            #pragma unroll
            for (int o = 16; o; o >>= 1) s += __shfl_xor_sync(0xFFFFFFFFu, s, o);
            float lse = mx + logf(s);
            m[lane][c] = x0 - lse;
            m[lane + 32][c] = x1 - lse;
        }
        __syncthreads();
    }
    for (int i = tid; i < 4096; i += 1024) {
        float e = expf(m[i >> 6][i & 63]);
        g_attn[(size_t)b * 4096 + i] = e;
        if (attn_out) attn_out[(size_t)b * 4096 + i] = e;
    }
}

// ---------------- attended = attn @ V, fused mix ----------------------------
__global__ __launch_bounds__(256) void attended_kernel() {
    int d0 = blockIdx.x * 128;
    int b = blockIdx.y;
    __shared__ float attn_s[64][64];
    __shared__ float4 Vs[64][32];
    int tid = threadIdx.x;
    const float* ab = g_attn + (size_t)b * 4096;
    for (int i = tid; i < 4096; i += 256) attn_s[i >> 6][i & 63] = ab[i];
    const float* Vb = g_v + (size_t)b * NA * D;
    {
        int r = tid >> 5;
        int c = tid & 31;
        #pragma unroll
        for (int p = 0; p < 8; p++)
            Vs[r + p * 8][c] = *(const float4*)(Vb + (size_t)(r + p * 8) * D + d0 + c * 4);
    }
    __syncthreads();
    int tx = tid & 31, ty = tid >> 5;
    float4 acc[8];
    #pragma unroll
    for (int i = 0; i < 8; i++) acc[i] = make_float4(0.f, 0.f, 0.f, 0.f);
    for (int mm = 0; mm < 64; mm++) {
        float4 v4 = Vs[mm][tx];
        #pragma unroll
        for (int i = 0; i < 8; i++) {
            float a = attn_s[ty * 8 + i][mm];
            acc[i].x += a * v4.x;
            acc[i].y += a * v4.y;
            acc[i].z += a * v4.z;
            acc[i].w += a * v4.w;
        }
    }
    #pragma unroll
    for (int i = 0; i < 8; i++) {
        int n = ty * 8 + i;
        size_t off = ((size_t)(b * 64 + n)) * D + d0 + tx * 4;
        float4 nm = *(const float4*)(g_normed + off);
        float4 o;
        o.x = ID_PRESERVE * nm.x + (1.0f - ID_PRESERVE) * acc[i].x;
        o.y = ID_PRESERVE * nm.y + (1.0f - ID_PRESERVE) * acc[i].y;
        o.z = ID_PRESERVE * nm.z + (1.0f - ID_PRESERVE) * acc[i].z;
        o.w = ID_PRESERVE * nm.w + (1.0f - ID_PRESERVE) * acc[i].w;
        *(float4*)(g_mixed + off) = o;
    }
}

// ---------------- epilogue ---------------------------------------------------
__global__ __launch_bounds__(256) void epilogue_kernel(const float* __restrict__ x,
                                                       const float* __restrict__ biases,
                                                       const float* __restrict__ scales,
                                                       float* __restrict__ out) {
    __shared__ float red[8];
    int row = blockIdx.x;
    int n = row & 63;
    int tid = threadIdx.x;
    float sc = scales[n];
    const float4* mr = (const float4*)(g_mixed + (size_t)row * D);
    const float4* br = (const float4*)(biases + (size_t)n * D);
    float4 m0 = mr[tid], m1 = mr[tid + 256];
    float4 b0 = br[tid], b1 = br[tid + 256];
    float4 s0, s1;
    s0.x = (m0.x + b0.x) * sc; s0.y = (m0.y + b0.y) * sc;
    s0.z = (m0.z + b0.z) * sc; s0.w = (m0.w + b0.w) * sc;
    s1.x = (m1.x + b1.x) * sc; s1.y = (m1.y + b1.y) * sc;
    s1.z = (m1.z + b1.z) * sc; s1.w = (m1.w + b1.w) * sc;
    float ss = s0.x*s0.x + s0.y*s0.y + s0.z*s0.z + s0.w*s0.w
             + s1.x*s1.x + s1.y*s1.y + s1.z*s1.z + s1.w*s1.w;
    #pragma unroll
    for (int o = 16; o; o >>= 1) ss += __shfl_xor_sync(0xFFFFFFFFu, ss, o);
    if ((tid & 31) == 0) red[tid >> 5] = ss;
    __syncthreads();
    float tot = 0.f;
    #pragma unroll
    for (int i = 0; i < 8; i++) tot += red[i];
    float norm = sqrtf(tot);
    float inv = 1.0f / fmaxf(1.0f, norm / SIGNAL_BOUND);
    const float4* xr = (const float4*)(x + (size_t)row * D);
    float4 x0 = xr[tid], x1 = xr[tid + 256];
    float4 o0, o1;
    o0.x = x0.x + s0.x * inv; o0.y = x0.y + s0.y * inv;
    o0.z = x0.z + s0.z * inv; o0.w = x0.w + s0.w * inv;
    o1.x = x1.x + s1.x * inv; o1.y = x1.y + s1.y * inv;
    o1.z = x1.z + s1.z * inv; o1.w = x1.w + s1.w * inv;
    float4* outr = (float4*)(out + (size_t)row * D);
    outr[tid] = o0;
    outr[tid + 256] = o1;
}

// ---------------- launch -----------------------------------------------------
extern "C" void kernel_launch(void* const* d_in, const int* in_sizes, int n_in,
                              void* d_out, int out_size) {
    const float* agent_states  = (const float*)d_in[0];
    const float* ln_w          = (const float*)d_in[1];
    const float* ln_b          = (const float*)d_in[2];
    const float* wq            = (const float*)d_in[3];
    const float* bq            = (const float*)d_in[4];
    const float* wk            = (const float*)d_in[5];
    const float* bk            = (const float*)d_in[6];
    const float* wv            = (const float*)d_in[7];
    const float* bv            = (const float*)d_in[8];
    const float* agent_biases  = (const float*)d_in[9];
    const float* scale_factors = (const float*)d_in[10];
    float* out = (float*)d_out;
    float* attn_out = (out_size >= ROWS * D + BATCH * NA * NA) ? (out + (size_t)ROWS * D)
                                                               : nullptr;

    const int DYN_SMEM = GSTAGES * GSTAGE_BYTES;   // 96 KB
    cudaFuncSetAttribute(qkv_mma_kernel, cudaFuncAttributeMaxDynamicSharedMemorySize, DYN_SMEM);

    ln_kernel<<<ROWS, 256>>>(agent_states, ln_w, ln_b);
    conv_w_kernel<<<dim3(D, 3), 256>>>(wq, wk, wv);
    qkv_mma_kernel<<<dim3(D / GBN, ROWS / GBM, 3), 256, DYN_SMEM>>>(bq, bk, bv);
    scores_kernel<<<dim3(SCORE_KSPLIT, BATCH), 256>>>();
    sinkhorn_kernel<<<BATCH, 1024>>>(attn_out);
    attended_kernel<<<dim3(16, BATCH), 256>>>();
    epilogue_kernel<<<ROWS, 256>>>(agent_states, agent_biases, scale_factors, out);
}